// round 4
// baseline (speedup 1.0000x reference)
#include <cuda_runtime.h>
#include <cuda_fp16.h>
#include <cstdint>
#include <cstddef>

static constexpr int BB = 8, SSQ = 4096, DIN = 256, HH = 512;
static constexpr int M = BB * SSQ;        // 32768
static constexpr int KE = 768;            // [xh|xh|xl] K-concat
static constexpr int NG = 4 * HH;         // 2048
static constexpr float EPSF = 1e-6f;
static constexpr int LCH = 128, NCH = SSQ / LCH, NCHAIN = BB * HH;

static constexpr int PAD = 40;            // smem row stride in halfs (80 B) — LDSM conflict-free
static constexpr int BM = 128, BN = 256, BK = 32;
static constexpr int NKT = KE / BK;       // 24
static constexpr int A_BYTES = BM * PAD * 2;            // 10240
static constexpr int B_BYTES = BN * PAD * 2;            // 20480
static constexpr int STGB = A_BYTES + B_BYTES;          // 30720
static constexpr int NSTAGE = 3;
static constexpr int SMEM_DYN = NSTAGE * STGB;          // 92160

static __device__ __half g_Ah[(size_t)M * KE];     // 48 MB
static __device__ __half g_Bh[(size_t)NG * KE];    // 3 MB
static __device__ float  g_G[(size_t)M * NG];      // 256 MB gates (i,f,o,z)
static __device__ float  g_Pa[NCHAIN * NCH];
static __device__ float  g_Ci[NCHAIN * NCH];
static __device__ float  g_Ni[NCHAIN * NCH];

__device__ __forceinline__ uint32_t smem_u32(const void* p) {
    uint32_t a;
    asm("{ .reg .u64 t; cvta.to.shared.u64 t, %1; cvt.u32.u64 %0, t; }" : "=r"(a) : "l"(p));
    return a;
}

// ---------------- prep A: [xh | xh | xl], row-major K-contig ----------------
__global__ void xl_prepA(const float* __restrict__ x) {
    int gid = blockIdx.x * blockDim.x + threadIdx.x;       // M*64 threads, 4 k each
    int j = gid & 63, m = gid >> 6;
    int k = j * 4;
    float4 v = *reinterpret_cast<const float4*>(x + (size_t)m * DIN + k);
    __half h[4], l[4];
    float vv[4] = {v.x, v.y, v.z, v.w};
#pragma unroll
    for (int t = 0; t < 4; t++) {
        h[t] = __float2half_rn(vv[t]);
        l[t] = __float2half_rn(vv[t] - __half2float(h[t]));
    }
    __half* row = g_Ah + (size_t)m * KE;
    *reinterpret_cast<uint2*>(row + k)       = *reinterpret_cast<uint2*>(h);
    *reinterpret_cast<uint2*>(row + 256 + k) = *reinterpret_cast<uint2*>(h);
    *reinterpret_cast<uint2*>(row + 512 + k) = *reinterpret_cast<uint2*>(l);
}

// ---------------- prep B: rows n (gate*512+h), cols [Wh | Wl | Wh] ----------
__global__ void xl_prepB(const float* __restrict__ Wi, const float* __restrict__ Wf,
                         const float* __restrict__ Wo, const float* __restrict__ Wz) {
    int gid = blockIdx.x * blockDim.x + threadIdx.x;       // NG*192 threads, 4 keff each
    int j = gid % 192, n = gid / 192;
    int keff = j * 4;
    int reg = keff >> 8;                                   // 0:hi 1:lo 2:hi
    int ks = keff & 255;
    int g = n >> 9, nc = n & 511;
    const float* W = (g == 0) ? Wi : (g == 1) ? Wf : (g == 2) ? Wo : Wz;
    __half out[4];
#pragma unroll
    for (int t = 0; t < 4; t++) {
        float w = W[(size_t)(ks + t) * HH + nc];
        __half hi = __float2half_rn(w);
        out[t] = (reg == 1) ? __float2half_rn(w - __half2float(hi)) : hi;
    }
    *reinterpret_cast<uint2*>(g_Bh + (size_t)n * KE + keff) = *reinterpret_cast<uint2*>(out);
}

// ---------------- GEMM (ldmatrix + 3-stage cp.async) + activation epilogue ---
#define LDSM_X4(r, addr) \
    asm volatile("ldmatrix.sync.aligned.m8n8.x4.shared.b16 {%0,%1,%2,%3}, [%4];" \
        : "=r"((r)[0]), "=r"((r)[1]), "=r"((r)[2]), "=r"((r)[3]) : "r"(addr))

__global__ __launch_bounds__(256) void xl_gemm(const float* __restrict__ bi, const float* __restrict__ bfg,
                                               const float* __restrict__ bo, const float* __restrict__ bz) {
    extern __shared__ char smem[];
    const uint32_t sbase = smem_u32(smem);
    const int tid = threadIdx.x, lane = tid & 31, wid = tid >> 5;
    const int bm = blockIdx.y * BM, bn = blockIdx.x * BN;
    const int warp_m = (wid & 1) * 64, warp_n = (wid >> 1) * 64;
    const int grp = lane >> 2, tq = lane & 3;

    float acc[4][8][4];
#pragma unroll
    for (int a = 0; a < 4; a++)
#pragma unroll
        for (int b = 0; b < 8; b++)
#pragma unroll
            for (int c = 0; c < 4; c++) acc[a][b][c] = 0.f;

    // per-thread ldmatrix base offsets (PAD=40 halfs => conflict-free LDSM)
    const int rsel = (lane & 7) + ((lane >> 3) & 1) * 8;   // row within 16-row group
    const int csel = (lane >> 4) * 8;                      // k offset 0/8
    const uint32_t a_base = sbase + (uint32_t)((warp_m + rsel) * PAD + csel) * 2;
    const uint32_t b_base = sbase + A_BYTES + (uint32_t)((warp_n + rsel) * PAD + csel) * 2;

    auto issue = [&](int kt, int st) {
        uint32_t sa = sbase + st * STGB;
#pragma unroll
        for (int i = 0; i < 2; i++) {                      // A: 512 int4
            int idx = tid + i * 256;
            int r = idx >> 2, c = idx & 3;
            const __half* ga = g_Ah + (size_t)(bm + r) * KE + kt * BK + c * 8;
            asm volatile("cp.async.cg.shared.global [%0], [%1], 16;"
                :: "r"(sa + (uint32_t)(r * PAD + c * 8) * 2), "l"(ga));
        }
        uint32_t sb = sbase + st * STGB + A_BYTES;
#pragma unroll
        for (int i = 0; i < 4; i++) {                      // B: 1024 int4
            int idx = tid + i * 256;
            int r = idx >> 2, c = idx & 3;
            const __half* gb = g_Bh + (size_t)(bn + r) * KE + kt * BK + c * 8;
            asm volatile("cp.async.cg.shared.global [%0], [%1], 16;"
                :: "r"(sb + (uint32_t)(r * PAD + c * 8) * 2), "l"(gb));
        }
        asm volatile("cp.async.commit_group;" ::: "memory");
    };

    issue(0, 0);
    issue(1, 1);
    for (int kt = 0; kt < NKT; kt++) {
        int st = kt % NSTAGE;
        if (kt + 2 < NKT) {
            issue(kt + 2, (kt + 2) % NSTAGE);
            asm volatile("cp.async.wait_group 2;" ::: "memory");
        } else {
            asm volatile("cp.async.wait_group 0;" ::: "memory");
        }
        __syncthreads();
        uint32_t ab = a_base + st * STGB;
        uint32_t bb = b_base + st * STGB;
#pragma unroll
        for (int ks = 0; ks < BK; ks += 16) {
            uint32_t afr[4][4], bfr[4][4];
#pragma unroll
            for (int im = 0; im < 4; im++)
                LDSM_X4(afr[im], ab + (uint32_t)(im * 16 * PAD + ks) * 2);
#pragma unroll
            for (int ip = 0; ip < 4; ip++)
                LDSM_X4(bfr[ip], bb + (uint32_t)(ip * 16 * PAD + ks) * 2);
#pragma unroll
            for (int im = 0; im < 4; im++)
#pragma unroll
                for (int ip = 0; ip < 4; ip++) {
                    asm volatile(
                        "mma.sync.aligned.m16n8k16.row.col.f32.f16.f16.f32 "
                        "{%0,%1,%2,%3}, {%4,%5,%6,%7}, {%8,%9}, {%0,%1,%2,%3};"
                        : "+f"(acc[im][2 * ip][0]), "+f"(acc[im][2 * ip][1]),
                          "+f"(acc[im][2 * ip][2]), "+f"(acc[im][2 * ip][3])
                        : "r"(afr[im][0]), "r"(afr[im][1]), "r"(afr[im][2]), "r"(afr[im][3]),
                          "r"(bfr[ip][0]), "r"(bfr[ip][2]));
                    asm volatile(
                        "mma.sync.aligned.m16n8k16.row.col.f32.f16.f16.f32 "
                        "{%0,%1,%2,%3}, {%4,%5,%6,%7}, {%8,%9}, {%0,%1,%2,%3};"
                        : "+f"(acc[im][2 * ip + 1][0]), "+f"(acc[im][2 * ip + 1][1]),
                          "+f"(acc[im][2 * ip + 1][2]), "+f"(acc[im][2 * ip + 1][3])
                        : "r"(afr[im][0]), "r"(afr[im][1]), "r"(afr[im][2]), "r"(afr[im][3]),
                          "r"(bfr[ip][1]), "r"(bfr[ip][3]));
                }
        }
        __syncthreads();
    }

    // epilogue: gate constant per block (BN=256 fits inside one 512-wide gate)
    const int g = blockIdx.x >> 1;
    const float* bias = (g == 0) ? bi : (g == 1) ? bfg : (g == 2) ? bo : bz;
#pragma unroll
    for (int im = 0; im < 4; im++)
#pragma unroll
        for (int in = 0; in < 8; in++) {
            int row0 = bm + warp_m + im * 16 + grp;
            int col0 = bn + warp_n + in * 8 + tq * 2;
            float b0 = bias[col0 & (HH - 1)], b1 = bias[(col0 + 1) & (HH - 1)];
#pragma unroll
            for (int hrow = 0; hrow < 2; hrow++) {
                int row = row0 + hrow * 8;
                float a0 = acc[im][in][hrow * 2 + 0] + b0;
                float a1 = acc[im][in][hrow * 2 + 1] + b1;
                float2 o;
                if (g < 2) {
                    o.x = __expf(fminf(fmaxf(a0, -20.f), 0.f));
                    o.y = __expf(fminf(fmaxf(a1, -20.f), 0.f));
                } else if (g == 2) {
                    o.x = 1.f / (1.f + __expf(-a0));
                    o.y = 1.f / (1.f + __expf(-a1));
                } else {
                    float t0 = __expf(2.f * fminf(fmaxf(a0, -15.f), 15.f));
                    float t1 = __expf(2.f * fminf(fmaxf(a1, -15.f), 15.f));
                    o.x = __fdividef(t0 - 1.f, t0 + 1.f);
                    o.y = __fdividef(t1 - 1.f, t1 + 1.f);
                }
                *reinterpret_cast<float2*>(g_G + (size_t)row * NG + col0) = o;
            }
        }
}

// ---------------- scan pass 1: per-chunk local (P, C, N) ----------------
__global__ void xl_scan1() {
    int t = blockIdx.x * blockDim.x + threadIdx.x;   // 131072
    int h = t & 511, ch = (t >> 9) & 31, b = t >> 14;
    float P = 1.f, C = 0.f, N = 0.f;
    const float* base = g_G + ((size_t)(b * SSQ + ch * LCH)) * NG + h;
    for (int s = 0; s < LCH; s++) {
        const float* p = base + (size_t)s * NG;
        float iv = p[0], fv = p[512], zv = p[1536];
        C = fv * C + iv * zv;
        N = fv * N + iv;
        P *= fv;
    }
    int idx = (b * NCH + ch) * HH + h;
    g_Pa[idx] = P; g_Ci[idx] = C; g_Ni[idx] = N;
}

// ---------------- scan pass 2: chunk-level scan, overwrite with inits -------
__global__ void xl_scan2() {
    int t = blockIdx.x * blockDim.x + threadIdx.x;   // 4096
    int h = t & 511, b = t >> 9;
    float c = 0.f, n = 1.f;
    for (int ch = 0; ch < NCH; ch++) {
        int idx = (b * NCH + ch) * HH + h;
        float P = g_Pa[idx], Cl = g_Ci[idx], Nl = g_Ni[idx];
        g_Ci[idx] = c; g_Ni[idx] = n;
        c = P * c + Cl;
        n = P * n + Nl;
    }
}

// ---------------- scan pass 3: recompute with inits, emit h ----------------
__global__ void xl_scan3(float* __restrict__ out) {
    int t = blockIdx.x * blockDim.x + threadIdx.x;   // 131072
    int h = t & 511, ch = (t >> 9) & 31, b = t >> 14;
    int idx = (b * NCH + ch) * HH + h;
    float c = g_Ci[idx], n = g_Ni[idx];
    const float* base = g_G + ((size_t)(b * SSQ + ch * LCH)) * NG + h;
    float* ob = out + ((size_t)(b * SSQ + ch * LCH)) * HH + h;
    for (int s = 0; s < LCH; s++) {
        const float* p = base + (size_t)s * NG;
        float iv = p[0], fv = p[512], ov = p[1024], zv = p[1536];
        c = fv * c + iv * zv;
        n = fv * n + iv;
        ob[(size_t)s * HH] = ov * (c / (n + EPSF));
    }
}

extern "C" void kernel_launch(void* const* d_in, const int* in_sizes, int n_in,
                              void* d_out, int out_size) {
    const float* x  = (const float*)d_in[0];
    const float* Wi = (const float*)d_in[1];
    const float* bi = (const float*)d_in[2];
    const float* Wf = (const float*)d_in[3];
    const float* bf = (const float*)d_in[4];
    const float* Wo = (const float*)d_in[5];
    const float* bo = (const float*)d_in[6];
    const float* Wz = (const float*)d_in[7];
    const float* bz = (const float*)d_in[8];
    float* out = (float*)d_out;

    cudaFuncSetAttribute(xl_gemm, cudaFuncAttributeMaxDynamicSharedMemorySize, SMEM_DYN);

    xl_prepA<<<(M * 64) / 256, 256>>>(x);
    xl_prepB<<<(NG * 192) / 256, 256>>>(Wi, Wf, Wo, Wz);
    xl_gemm<<<dim3(NG / BN, M / BM), 256, SMEM_DYN>>>(bi, bf, bo, bz);
    xl_scan1<<<(NCHAIN * NCH) / 256, 256>>>();
    xl_scan2<<<NCHAIN / 256, 256>>>();
    xl_scan3<<<(NCHAIN * NCH) / 256, 256>>>(out);
}

// round 5
// speedup vs baseline: 1.5274x; 1.5274x over previous
#include <cuda_runtime.h>
#include <cuda_fp16.h>
#include <cstdint>
#include <cstddef>

static constexpr int BB = 8, SSQ = 4096, DIN = 256, HH = 512;
static constexpr int M = BB * SSQ;        // 32768
static constexpr int KE = 512;            // [xh | xl] K-concat
static constexpr int NG = 4 * HH;         // 2048
static constexpr float EPSF = 1e-6f;
static constexpr int LCH = 128, NCH = SSQ / LCH, NCHAIN = BB * HH;

static constexpr int PAD = 40;            // smem row stride (halfs); LDSM conflict-free
static constexpr int BM = 128, BN = 128, BK = 32;
static constexpr int NKT = KE / BK;       // 16
static constexpr int A_BYTES = BM * PAD * 2;   // 10240
static constexpr int B_BYTES = BN * PAD * 2;   // 10240
static constexpr int STGB = A_BYTES + B_BYTES; // 20480
static constexpr int NSTAGE = 4;
static constexpr int SMEM_DYN = NSTAGE * STGB; // 81920

static __device__ __half g_Ah[(size_t)M * KE];     // 32 MB
static __device__ __half g_Bh[(size_t)NG * KE];    // 2 MB
static __device__ float  g_G[(size_t)M * NG];      // 256 MB gates (i,f,o,z)
static __device__ float  g_Pa[NCHAIN * NCH];
static __device__ float  g_Ci[NCHAIN * NCH];
static __device__ float  g_Ni[NCHAIN * NCH];

__device__ __forceinline__ uint32_t smem_u32(const void* p) {
    uint32_t a;
    asm("{ .reg .u64 t; cvta.to.shared.u64 t, %1; cvt.u32.u64 %0, t; }" : "=r"(a) : "l"(p));
    return a;
}

// ---------------- prep A: [xh | xl], row-major K-contig ----------------
__global__ void xl_prepA(const float* __restrict__ x) {
    int gid = blockIdx.x * blockDim.x + threadIdx.x;       // M*64 threads, 4 src k each
    int j = gid & 63, m = gid >> 6;
    int k = j * 4;
    float4 v = *reinterpret_cast<const float4*>(x + (size_t)m * DIN + k);
    __half h[4], l[4];
    float vv[4] = {v.x, v.y, v.z, v.w};
#pragma unroll
    for (int t = 0; t < 4; t++) {
        h[t] = __float2half_rn(vv[t]);
        l[t] = __float2half_rn(vv[t] - __half2float(h[t]));
    }
    __half* row = g_Ah + (size_t)m * KE;
    *reinterpret_cast<uint2*>(row + k)       = *reinterpret_cast<uint2*>(h);
    *reinterpret_cast<uint2*>(row + 256 + k) = *reinterpret_cast<uint2*>(l);
}

// ---------------- prep B: rows n (gate*512+h), cols [Wh ; Wh] ----------
__global__ void xl_prepB(const float* __restrict__ Wi, const float* __restrict__ Wf,
                         const float* __restrict__ Wo, const float* __restrict__ Wz) {
    int gid = blockIdx.x * blockDim.x + threadIdx.x;       // NG*128 threads, 4 keff each
    int j = gid & 127, n = gid >> 7;
    int keff = j * 4;
    int ks = keff & 255;
    int g = n >> 9, nc = n & 511;
    const float* W = (g == 0) ? Wi : (g == 1) ? Wf : (g == 2) ? Wo : Wz;
    __half out[4];
#pragma unroll
    for (int t = 0; t < 4; t++)
        out[t] = __float2half_rn(W[(size_t)(ks + t) * HH + nc]);
    *reinterpret_cast<uint2*>(g_Bh + (size_t)n * KE + keff) = *reinterpret_cast<uint2*>(out);
}

// ---------------- GEMM (ldmatrix + 4-stage cp.async) + activation epilogue ---
#define LDSM_X4(r, addr) \
    asm volatile("ldmatrix.sync.aligned.m8n8.x4.shared.b16 {%0,%1,%2,%3}, [%4];" \
        : "=r"((r)[0]), "=r"((r)[1]), "=r"((r)[2]), "=r"((r)[3]) : "r"(addr))

__global__ __launch_bounds__(256, 2) void xl_gemm(const float* __restrict__ bi, const float* __restrict__ bfg,
                                                  const float* __restrict__ bo, const float* __restrict__ bz) {
    extern __shared__ char smem[];
    const uint32_t sbase = smem_u32(smem);
    const int tid = threadIdx.x, lane = tid & 31, wid = tid >> 5;
    const int bm = blockIdx.y * BM, bn = blockIdx.x * BN;
    const int warp_m = (wid & 1) * 64, warp_n = (wid >> 1) * 32;
    const int grp = lane >> 2, tq = lane & 3;

    float acc[4][4][4];
#pragma unroll
    for (int a = 0; a < 4; a++)
#pragma unroll
        for (int b = 0; b < 4; b++)
#pragma unroll
            for (int c = 0; c < 4; c++) acc[a][b][c] = 0.f;

    // ldmatrix per-lane addressing (verified correct in R4)
    const int rsel = (lane & 7) + ((lane >> 3) & 1) * 8;
    const int csel = (lane >> 4) * 8;
    const uint32_t a_base = sbase + (uint32_t)((warp_m + rsel) * PAD + csel) * 2;
    const uint32_t b_base = sbase + A_BYTES + (uint32_t)((warp_n + rsel) * PAD + csel) * 2;

    auto issue = [&](int kt, int st) {
        uint32_t sa = sbase + st * STGB;
#pragma unroll
        for (int i = 0; i < 2; i++) {                      // A: 512 int4
            int idx = tid + i * 256;
            int r = idx >> 2, c = idx & 3;
            const __half* ga = g_Ah + (size_t)(bm + r) * KE + kt * BK + c * 8;
            asm volatile("cp.async.cg.shared.global [%0], [%1], 16;"
                :: "r"(sa + (uint32_t)(r * PAD + c * 8) * 2), "l"(ga));
        }
        uint32_t sb = sbase + st * STGB + A_BYTES;
#pragma unroll
        for (int i = 0; i < 2; i++) {                      // B: 512 int4
            int idx = tid + i * 256;
            int r = idx >> 2, c = idx & 3;
            const __half* gb = g_Bh + (size_t)(bn + r) * KE + kt * BK + c * 8;
            asm volatile("cp.async.cg.shared.global [%0], [%1], 16;"
                :: "r"(sb + (uint32_t)(r * PAD + c * 8) * 2), "l"(gb));
        }
        asm volatile("cp.async.commit_group;" ::: "memory");
    };

    issue(0, 0); issue(1, 1); issue(2, 2);
    for (int kt = 0; kt < NKT; kt++) {
        int st = kt & 3;
        if (kt + 3 < NKT) {
            issue(kt + 3, (kt + 3) & 3);
            asm volatile("cp.async.wait_group 3;" ::: "memory");
        } else {
            asm volatile("cp.async.wait_group 0;" ::: "memory");
        }
        __syncthreads();
        uint32_t ab = a_base + st * STGB;
        uint32_t bb = b_base + st * STGB;
#pragma unroll
        for (int ks = 0; ks < BK; ks += 16) {
            uint32_t afr[4][4], bfr[2][4];
#pragma unroll
            for (int im = 0; im < 4; im++)
                LDSM_X4(afr[im], ab + (uint32_t)(im * 16 * PAD + ks) * 2);
#pragma unroll
            for (int ip = 0; ip < 2; ip++)
                LDSM_X4(bfr[ip], bb + (uint32_t)(ip * 16 * PAD + ks) * 2);
#pragma unroll
            for (int im = 0; im < 4; im++)
#pragma unroll
                for (int ip = 0; ip < 2; ip++) {
                    asm volatile(
                        "mma.sync.aligned.m16n8k16.row.col.f32.f16.f16.f32 "
                        "{%0,%1,%2,%3}, {%4,%5,%6,%7}, {%8,%9}, {%0,%1,%2,%3};"
                        : "+f"(acc[im][2 * ip][0]), "+f"(acc[im][2 * ip][1]),
                          "+f"(acc[im][2 * ip][2]), "+f"(acc[im][2 * ip][3])
                        : "r"(afr[im][0]), "r"(afr[im][1]), "r"(afr[im][2]), "r"(afr[im][3]),
                          "r"(bfr[ip][0]), "r"(bfr[ip][2]));
                    asm volatile(
                        "mma.sync.aligned.m16n8k16.row.col.f32.f16.f16.f32 "
                        "{%0,%1,%2,%3}, {%4,%5,%6,%7}, {%8,%9}, {%0,%1,%2,%3};"
                        : "+f"(acc[im][2 * ip + 1][0]), "+f"(acc[im][2 * ip + 1][1]),
                          "+f"(acc[im][2 * ip + 1][2]), "+f"(acc[im][2 * ip + 1][3])
                        : "r"(afr[im][0]), "r"(afr[im][1]), "r"(afr[im][2]), "r"(afr[im][3]),
                          "r"(bfr[ip][1]), "r"(bfr[ip][3]));
                }
        }
        __syncthreads();
    }

    // epilogue: gate constant per block (4 blocks of 128 per gate)
    const int g = blockIdx.x >> 2;
    const float* bias = (g == 0) ? bi : (g == 1) ? bfg : (g == 2) ? bo : bz;
#pragma unroll
    for (int im = 0; im < 4; im++)
#pragma unroll
        for (int in = 0; in < 4; in++) {
            int row0 = bm + warp_m + im * 16 + grp;
            int col0 = bn + warp_n + in * 8 + tq * 2;
            float b0 = bias[col0 & (HH - 1)], b1 = bias[(col0 + 1) & (HH - 1)];
#pragma unroll
            for (int hrow = 0; hrow < 2; hrow++) {
                int row = row0 + hrow * 8;
                float a0 = acc[im][in][hrow * 2 + 0] + b0;
                float a1 = acc[im][in][hrow * 2 + 1] + b1;
                float2 o;
                if (g < 2) {
                    o.x = __expf(fminf(fmaxf(a0, -20.f), 0.f));
                    o.y = __expf(fminf(fmaxf(a1, -20.f), 0.f));
                } else if (g == 2) {
                    o.x = 1.f / (1.f + __expf(-a0));
                    o.y = 1.f / (1.f + __expf(-a1));
                } else {
                    float t0 = __expf(2.f * fminf(fmaxf(a0, -15.f), 15.f));
                    float t1 = __expf(2.f * fminf(fmaxf(a1, -15.f), 15.f));
                    o.x = __fdividef(t0 - 1.f, t0 + 1.f);
                    o.y = __fdividef(t1 - 1.f, t1 + 1.f);
                }
                *reinterpret_cast<float2*>(g_G + (size_t)row * NG + col0) = o;
            }
        }
}

// ---------------- scan pass 1: per-chunk local (P, C, N) ----------------
__global__ void xl_scan1() {
    int t = blockIdx.x * blockDim.x + threadIdx.x;   // 131072
    int h = t & 511, ch = (t >> 9) & 31, b = t >> 14;
    float P = 1.f, C = 0.f, N = 0.f;
    const float* base = g_G + ((size_t)(b * SSQ + ch * LCH)) * NG + h;
    for (int s = 0; s < LCH; s++) {
        const float* p = base + (size_t)s * NG;
        float iv = p[0], fv = p[512], zv = p[1536];
        C = fv * C + iv * zv;
        N = fv * N + iv;
        P *= fv;
    }
    int idx = (b * NCH + ch) * HH + h;
    g_Pa[idx] = P; g_Ci[idx] = C; g_Ni[idx] = N;
}

// ---------------- scan pass 2: chunk-level scan, overwrite with inits -------
__global__ void xl_scan2() {
    int t = blockIdx.x * blockDim.x + threadIdx.x;   // 4096
    int h = t & 511, b = t >> 9;
    float c = 0.f, n = 1.f;
    for (int ch = 0; ch < NCH; ch++) {
        int idx = (b * NCH + ch) * HH + h;
        float P = g_Pa[idx], Cl = g_Ci[idx], Nl = g_Ni[idx];
        g_Ci[idx] = c; g_Ni[idx] = n;
        c = P * c + Cl;
        n = P * n + Nl;
    }
}

// ---------------- scan pass 3: recompute with inits, emit h ----------------
__global__ void xl_scan3(float* __restrict__ out) {
    int t = blockIdx.x * blockDim.x + threadIdx.x;   // 131072
    int h = t & 511, ch = (t >> 9) & 31, b = t >> 14;
    int idx = (b * NCH + ch) * HH + h;
    float c = g_Ci[idx], n = g_Ni[idx];
    const float* base = g_G + ((size_t)(b * SSQ + ch * LCH)) * NG + h;
    float* ob = out + ((size_t)(b * SSQ + ch * LCH)) * HH + h;
    for (int s = 0; s < LCH; s++) {
        const float* p = base + (size_t)s * NG;
        float iv = p[0], fv = p[512], ov = p[1024], zv = p[1536];
        c = fv * c + iv * zv;
        n = fv * n + iv;
        ob[(size_t)s * HH] = ov * (c / (n + EPSF));
    }
}

extern "C" void kernel_launch(void* const* d_in, const int* in_sizes, int n_in,
                              void* d_out, int out_size) {
    const float* x  = (const float*)d_in[0];
    const float* Wi = (const float*)d_in[1];
    const float* bi = (const float*)d_in[2];
    const float* Wf = (const float*)d_in[3];
    const float* bf = (const float*)d_in[4];
    const float* Wo = (const float*)d_in[5];
    const float* bo = (const float*)d_in[6];
    const float* Wz = (const float*)d_in[7];
    const float* bz = (const float*)d_in[8];
    float* out = (float*)d_out;

    cudaFuncSetAttribute(xl_gemm, cudaFuncAttributeMaxDynamicSharedMemorySize, SMEM_DYN);

    xl_prepA<<<(M * 64) / 256, 256>>>(x);
    xl_prepB<<<(NG * 128) / 256, 256>>>(Wi, Wf, Wo, Wz);
    xl_gemm<<<dim3(NG / BN, M / BM), 256, SMEM_DYN>>>(bi, bf, bo, bz);
    xl_scan1<<<(NCHAIN * NCH) / 256, 256>>>();
    xl_scan2<<<NCHAIN / 256, 256>>>();
    xl_scan3<<<(NCHAIN * NCH) / 256, 256>>>(out);
}